// round 9
// baseline (speedup 1.0000x reference)
#include <cuda_runtime.h>
#include <cuda_bf16.h>
#include <cstdint>

// Problem constants
#define NUM_EMB   1024
#define DIM       64
#define N_TOKENS  65536
#define BM        128          // tokens per CTA
#define BN        128          // codes per chunk
#define NCH       8            // 1024/128
#define PAD       68
#define NTHR      256          // 8 warps

// Output layout (single fp32 buffer)
#define OFF_Q     1
#define OFF_PPL   (1 + N_TOKENS*DIM)
#define OFF_IDX   (2 + N_TOKENS*DIM)

typedef unsigned long long ull;

// Device state
__device__ __nv_bfloat16 g_wsp[NUM_EMB * 128];  // per code: [e1(64) | e2(64)]
__device__ float    g_ensq[NUM_EMB];
__device__ float    g_counts[NUM_EMB];
__device__ float    g_loss_sum;
__device__ unsigned g_ticket;

// ---------------------------------------------------------------------------
// smem layout (bytes)
#define SM_AB     0                        // bf16 [x1|x2]: 128*256 = 32768
#define SM_B      32768                    // 2 bufs * 128*256 = 65536
#define SM_EN     98304                    // 1024 floats (biased +1) = 4096
#define SM_XSQ    102400                   // 128 floats -> 512
#define SM_IDX    102912                   // 128 ints -> 512
#define SM_PART   103424                   // 256 floats = 1024
#define SM_TICK   104448
#define SM_TOTAL  104464

// ---------------------------------------------------------------------------
#define LDSM_X4(r0,r1,r2,r3,addr) \
  asm volatile("ldmatrix.sync.aligned.m8n8.x4.shared.b16 {%0,%1,%2,%3}, [%4];" \
    : "=r"(r0),"=r"(r1),"=r"(r2),"=r"(r3) : "r"(addr))

#define MMA16816(d,a,b0,b1) \
  asm volatile("mma.sync.aligned.m16n8k16.row.col.f32.bf16.bf16.f32 " \
    "{%0,%1,%2,%3},{%4,%5,%6,%7},{%8,%9},{%0,%1,%2,%3};" \
    : "+f"((d)[0]),"+f"((d)[1]),"+f"((d)[2]),"+f"((d)[3]) \
    : "r"((a)[0]),"r"((a)[1]),"r"((a)[2]),"r"((a)[3]),"r"(b0),"r"(b1))

__device__ __forceinline__ void cp16(unsigned saddr, const void* gaddr) {
    asm volatile("cp.async.cg.shared.global [%0], [%1], 16;" :: "r"(saddr), "l"(gaddr));
}
#define CP_COMMIT() asm volatile("cp.async.commit_group;" ::: "memory")
#define CP_WAIT1()  asm volatile("cp.async.wait_group 1;" ::: "memory")
#define CP_WAIT0()  asm volatile("cp.async.wait_group 0;" ::: "memory")
__device__ __forceinline__ float ldcg(const float* p) {
    float v; asm volatile("ld.global.cg.f32 %0, [%1];" : "=f"(v) : "l"(p)); return v;
}

// top-3 key insert (smaller key = better (metric, idx))
__device__ __forceinline__ void ins3(ull& t0, ull& t1, ull& t2, ull k) {
    if (k < t2) {
        if (k < t0)      { t2 = t1; t1 = t0; t0 = k; }
        else if (k < t1) { t2 = t1; t1 = k; }
        else               t2 = k;
    }
}
__device__ __forceinline__ ull mkkey(float s, int idx) {
    return ((ull)__float_as_uint(s) << 10) | (unsigned)idx;
}
__device__ __forceinline__ float keysc(ull k) {
    return __uint_as_float((unsigned)(k >> 10));
}

// ---------------------------------------------------------------------------
// k_prep: W exact 2-way bf16 split + code norms (sequential unfused = ref)
// ---------------------------------------------------------------------------
__global__ void k_prep(const float* __restrict__ weight) {
    __shared__ float sw[128 * PAD];
    const int tid = threadIdx.x;             // 128
    const int b   = blockIdx.x;              // 8
    const float* g = weight + (size_t)b * 128 * DIM;
#pragma unroll
    for (int i = 0; i < 64; ++i) {
        int e = tid + i * 128;
        sw[(e >> 6) * PAD + (e & 63)] = g[e];
    }
    __syncthreads();
    const int k = b * 128 + tid;
    const float* x = sw + tid * PAD;
    float s = 0.f;
#pragma unroll
    for (int d = 0; d < DIM; ++d) {
        float v = x[d];
        s = __fadd_rn(s, __fmul_rn(v, v));
        __nv_bfloat16 e1 = __float2bfloat16_rn(v);
        float r1 = v - __bfloat162float(e1);
        __nv_bfloat16 e2 = __float2bfloat16_rn(r1);
        g_wsp[(size_t)k * 128 + d]      = e1;
        g_wsp[(size_t)k * 128 + 64 + d] = e2;
    }
    g_ensq[k] = s;
}

// ---------------------------------------------------------------------------
// k_main: 3-term bf16-split mma.sync pruning GEMM + exact-rescore argmin
// ---------------------------------------------------------------------------
__global__ __launch_bounds__(NTHR, 2)
void k_main(const float* __restrict__ inputs,
            const float* __restrict__ weight,
            float* __restrict__ out) {
    extern __shared__ char smem[];
    float* s_en  = (float*)(smem + SM_EN);    // 1 + ensq (biased)
    float* s_xsq = (float*)(smem + SM_XSQ);
    int*   s_idx = (int*)  (smem + SM_IDX);
    float* s_part= (float*)(smem + SM_PART);
    unsigned* s_tick = (unsigned*)(smem + SM_TICK);

    const uint32_t sbase = (uint32_t)__cvta_generic_to_shared(smem);
    const int tid  = threadIdx.x;
    const int w    = tid >> 5;
    const int lane = tid & 31;
    const int tok0 = blockIdx.x * BM;

    // --- prefetch B chunk 0: [e1|e2] rows (256B), SW swizzled ---
#pragma unroll
    for (int it = 0; it < 8; ++it) {
        int e = tid + it * NTHR;             // 0..2047
        int row = e >> 4, g = e & 15;
        uint32_t dst = sbase + SM_B + row * 256 + ((g >> 3) << 7)
                     + ((((g & 7) ^ (row & 7)) << 4));
        cp16(dst, g_wsp + ((size_t)row << 7) + g * 8);
    }
    CP_COMMIT();

    // --- biased code norms (1 + ensq) ---
#pragma unroll
    for (int it = 0; it < 4; ++it) {
        int e = tid + it * NTHR;
        s_en[e] = 1.0f + g_ensq[e];
    }

    // --- A exact 2-way bf16 split (d-pairs, packed STS.32) ---
    {
        const float2* gx2 = (const float2*)(inputs + (size_t)tok0 * DIM);
#pragma unroll
        for (int it = 0; it < 16; ++it) {
            int e = tid + it * NTHR;         // 0..4095 pairs
            int row = e >> 5, p = e & 31;
            int d = p * 2;
            float2 v = __ldg(gx2 + e);
            __nv_bfloat16 x1a = __float2bfloat16_rn(v.x);
            __nv_bfloat16 x1b = __float2bfloat16_rn(v.y);
            float r1a = v.x - __bfloat162float(x1a);
            float r1b = v.y - __bfloat162float(x1b);
            __nv_bfloat16 x2a = __float2bfloat16_rn(r1a);
            __nv_bfloat16 x2b = __float2bfloat16_rn(r1b);
            uint32_t p1 = (uint32_t)*(uint16_t*)&x1a | ((uint32_t)*(uint16_t*)&x1b << 16);
            uint32_t p2 = (uint32_t)*(uint16_t*)&x2a | ((uint32_t)*(uint16_t*)&x2b << 16);
            uint32_t sw = (uint32_t)((((d >> 3) & 7) ^ (row & 7)) << 4)
                        | (uint32_t)((d * 2) & 15);
            *(uint32_t*)(smem + SM_AB + row * 256 + sw)       = p1;
            *(uint32_t*)(smem + SM_AB + row * 256 + 128 + sw) = p2;
        }
    }

    // --- ||x||^2: sequential UNFUSED (replicates reference rounding) ---
    if (tid < BM) {
        const float* x = inputs + (size_t)(tok0 + tid) * DIM;
        float s = 0.f;
#pragma unroll
        for (int d = 0; d < DIM; ++d) {
            float v = __ldg(x + d);
            s = __fadd_rn(s, __fmul_rn(v, v));
        }
        s_xsq[tid] = s;
    }
    __syncthreads();

    // --- per-warp A fragments in registers: m16 x k128 ([x1|x2]) ---
    uint32_t afr[8][4];
    {
        const int tr = lane & 15;
        const int kadd = (lane >> 4) * 16;
#pragma unroll
        for (int u = 0; u < 8; ++u) {
            int kb = u * 32 + kadd;
            uint32_t addr = sbase + SM_AB + (w * 16 + tr) * 256 + (kb & 128)
                          + (((((kb >> 4) & 7) ^ (tr & 7)) << 4));
            LDSM_X4(afr[u][0], afr[u][1], afr[u][2], afr[u][3], addr);
        }
    }

    // --- B lane address offsets (i=0,1 -> e1; i=2,3 -> e2) ---
    const int cr = lane & 7;
    const int klane = (lane >> 3) & 3;
    uint32_t boff[4];
#pragma unroll
    for (int i = 0; i < 4; ++i) {
        int kb = i * 64 + klane * 16;
        boff[i] = (uint32_t)(cr * 256 + (kb & 128)
                + (((((kb >> 4) & 7) ^ cr) << 4)));
    }

    const float xq_lo = s_xsq[w * 16 + (lane >> 2)];
    const float xq_hi = s_xsq[w * 16 + (lane >> 2) + 8];
    ull kLo0 = mkkey(3.4e38f, 1023), kLo1 = kLo0, kLo2 = kLo0;
    ull kHi0 = kLo0,                 kHi1 = kLo0, kHi2 = kLo0;
    float t2Lo = 3.4e38f, t2Hi = 3.4e38f;   // cached third-best scores

    const float2* enp = (const float2*)s_en;
    const int enl = lane & 3;

    for (int c = 0; c < NCH; ++c) {
        if (c + 1 < NCH) {
            const uint32_t dst0 = sbase + SM_B + ((c + 1) & 1) * 32768;
            const size_t srow = (size_t)(c + 1) * BN;
#pragma unroll
            for (int it = 0; it < 8; ++it) {
                int e = tid + it * NTHR;
                int row = e >> 4, g = e & 15;
                uint32_t dst = dst0 + row * 256 + ((g >> 3) << 7)
                             + ((((g & 7) ^ (row & 7)) << 4));
                cp16(dst, g_wsp + ((srow + row) << 7) + g * 8);
            }
            CP_COMMIT();
            CP_WAIT1();
        } else {
            CP_COMMIT();
            CP_WAIT0();
        }
        __syncthreads();

        const uint32_t bbuf = sbase + SM_B + (c & 1) * 32768;

#pragma unroll 1
        for (int s8 = 0; s8 < 8; ++s8) {
            const int n0a = s8 * 16;
            const int n0b = n0a + 8;
            // 6 independent accumulator chains (3 phases x 2 columns)
            float d1A[4] = {0,0,0,0}, d2A[4] = {0,0,0,0}, d3A[4] = {0,0,0,0};
            float d1B[4] = {0,0,0,0}, d2B[4] = {0,0,0,0}, d3B[4] = {0,0,0,0};
            uint32_t fa[8], fb[8];

            // ---- e1 fragments -> x1.e1 (d1), x2.e1 (d3) ----
            LDSM_X4(fa[0],fa[1],fa[2],fa[3], bbuf + n0a * 256 + boff[0]);
            LDSM_X4(fa[4],fa[5],fa[6],fa[7], bbuf + n0a * 256 + boff[1]);
            LDSM_X4(fb[0],fb[1],fb[2],fb[3], bbuf + n0b * 256 + boff[0]);
            LDSM_X4(fb[4],fb[5],fb[6],fb[7], bbuf + n0b * 256 + boff[1]);
#pragma unroll
            for (int j = 0; j < 4; ++j) {
                MMA16816(d1A, afr[j],   fa[2*j], fa[2*j+1]);
                MMA16816(d1B, afr[j],   fb[2*j], fb[2*j+1]);
                MMA16816(d3A, afr[4+j], fa[2*j], fa[2*j+1]);
                MMA16816(d3B, afr[4+j], fb[2*j], fb[2*j+1]);
            }
            // ---- e2 fragments -> x1.e2 (d2) ----
            LDSM_X4(fa[0],fa[1],fa[2],fa[3], bbuf + n0a * 256 + boff[2]);
            LDSM_X4(fa[4],fa[5],fa[6],fa[7], bbuf + n0a * 256 + boff[3]);
            LDSM_X4(fb[0],fb[1],fb[2],fb[3], bbuf + n0b * 256 + boff[2]);
            LDSM_X4(fb[4],fb[5],fb[6],fb[7], bbuf + n0b * 256 + boff[3]);
#pragma unroll
            for (int j = 0; j < 4; ++j) {
                MMA16816(d2A, afr[j],   fa[2*j], fa[2*j+1]);
                MMA16816(d2B, afr[j],   fb[2*j], fb[2*j+1]);
            }

            // approx metric m = fl((1+ensq) - 2*dot); group-min prefilter
            float2 enA = enp[c * 64 + s8 * 8 + enl];
            float2 enB = enp[c * 64 + s8 * 8 + 4 + enl];
            float sA0 = fmaf(-2.f, (d1A[0] + d2A[0]) + d3A[0], enA.x);
            float sA1 = fmaf(-2.f, (d1A[1] + d2A[1]) + d3A[1], enA.y);
            float sA2 = fmaf(-2.f, (d1A[2] + d2A[2]) + d3A[2], enA.x);
            float sA3 = fmaf(-2.f, (d1A[3] + d2A[3]) + d3A[3], enA.y);
            float sB0 = fmaf(-2.f, (d1B[0] + d2B[0]) + d3B[0], enB.x);
            float sB1 = fmaf(-2.f, (d1B[1] + d2B[1]) + d3B[1], enB.y);
            float sB2 = fmaf(-2.f, (d1B[2] + d2B[2]) + d3B[2], enB.x);
            float sB3 = fmaf(-2.f, (d1B[3] + d2B[3]) + d3B[3], enB.y);

            float mLo = fminf(fminf(sA0, sA1), fminf(sB0, sB1));
            float mHi = fminf(fminf(sA2, sA3), fminf(sB2, sB3));

            if (mLo <= t2Lo) {
                int colA = c * BN + n0a + enl * 2;
                ins3(kLo0, kLo1, kLo2, mkkey(sA0, colA));
                ins3(kLo0, kLo1, kLo2, mkkey(sA1, colA + 1));
                ins3(kLo0, kLo1, kLo2, mkkey(sB0, colA + 8));
                ins3(kLo0, kLo1, kLo2, mkkey(sB1, colA + 9));
                t2Lo = keysc(kLo2);
            }
            if (mHi <= t2Hi) {
                int colA = c * BN + n0a + enl * 2;
                ins3(kHi0, kHi1, kHi2, mkkey(sA2, colA));
                ins3(kHi0, kHi1, kHi2, mkkey(sA3, colA + 1));
                ins3(kHi0, kHi1, kHi2, mkkey(sB2, colA + 8));
                ins3(kHi0, kHi1, kHi2, mkkey(sB3, colA + 9));
                t2Hi = keysc(kHi2);
            }
        }
        __syncthreads();
    }

    // --- winner resolution: window filter + exact (round-1) rescore ---
#pragma unroll
    for (int half = 0; half < 2; ++half) {
        ull k0 = half ? kHi0 : kLo0;
        ull k1 = half ? kHi1 : kLo1;
        ull k2 = half ? kHi2 : kLo2;
        float xq = half ? xq_hi : xq_lo;
        int trow = w * 16 + (lane >> 2) + half * 8;

        ull m = k0, o;
        o = __shfl_xor_sync(0xffffffffu, m, 1); m = o < m ? o : m;
        o = __shfl_xor_sync(0xffffffffu, m, 2); m = o < m ? o : m;
        float win = keysc(m) + 2e-5f;

        float s0f = keysc(k0), s1f = keysc(k1), s2f = keysc(k2);
        int cnt = (int)(s0f <= win) + (int)(s1f <= win) + (int)(s2f <= win);
        cnt += __shfl_xor_sync(0xffffffffu, cnt, 1);
        cnt += __shfl_xor_sync(0xffffffffu, cnt, 2);

        ull ebest = ~0ull;
        if (cnt > 1) {
            const float* xrow = inputs + (size_t)(tok0 + trow) * DIM;
            ull   ks[3] = {k0, k1, k2};
            float sf[3] = {s0f, s1f, s2f};
#pragma unroll 1
            for (int j = 0; j < 3; ++j) {
                if (sf[j] <= win) {
                    int idx = (int)(ks[j] & 1023);
                    const float* wrow = weight + (size_t)idx * DIM;
                    float aLo = 0.f, aHi = 0.f;
#pragma unroll
                    for (int d = 0; d < 32; ++d) {
                        aLo = fmaf(__ldg(xrow + 2*d),     __ldg(wrow + 2*d),     aLo);
                        aHi = fmaf(__ldg(xrow + 2*d + 1), __ldg(wrow + 2*d + 1), aHi);
                    }
                    float dot = __fadd_rn(aLo, aHi);
                    float es = fmaf(-2.f, dot, __fadd_rn(xq, ldcg(&g_ensq[idx])));
                    ull ek = mkkey(es, idx);
                    if (ek < ebest) ebest = ek;
                }
            }
        }
        o = __shfl_xor_sync(0xffffffffu, ebest, 1); ebest = o < ebest ? o : ebest;
        o = __shfl_xor_sync(0xffffffffu, ebest, 2); ebest = o < ebest ? o : ebest;

        int widx = (cnt == 1) ? (int)(m & 1023) : (int)(ebest & 1023);
        if ((lane & 3) == 0) {
            s_idx[trow] = widx;
            out[OFF_IDX + (size_t)(tok0 + trow)] = (float)widx;
            atomicAdd(&g_counts[widx], 1.f);
        }
    }
    __syncthreads();

    // --- gather codes -> quantized output + loss partial (float4 loads) ---
    float local = 0.f;
    {
        const float4* gx4 = (const float4*)(inputs + (size_t)tok0 * DIM);
#pragma unroll
        for (int it = 0; it < 8; ++it) {
            int t  = it * 16 + (tid >> 4);   // token 0..127
            int dq = tid & 15;               // float4 lane 0..15
            float4 qv = __ldg((const float4*)(weight + (size_t)s_idx[t] * DIM) + dq);
            float4 xv = __ldg(gx4 + t * 16 + dq);
            size_t ob = OFF_Q + (size_t)(tok0 + t) * DIM + dq * 4;
            out[ob]     = qv.x;
            out[ob + 1] = qv.y;
            out[ob + 2] = qv.z;
            out[ob + 3] = qv.w;
            float da = qv.x - xv.x, db = qv.y - xv.y;
            float dc = qv.z - xv.z, dd = qv.w - xv.w;
            local = fmaf(da, da, local);
            local = fmaf(db, db, local);
            local = fmaf(dc, dc, local);
            local = fmaf(dd, dd, local);
        }
    }
    s_part[tid] = local;
    __syncthreads();
    for (int off = 128; off > 0; off >>= 1) {
        if (tid < off) s_part[tid] += s_part[tid + off];
        __syncthreads();
    }
    if (tid == 0) atomicAdd(&g_loss_sum, s_part[0]);

    // --- last-block finalization (ticket) ---
    __threadfence();
    if (tid == 0) *s_tick = atomicAdd(&g_ticket, 1u);
    __syncthreads();
    if (*s_tick == (unsigned)(gridDim.x - 1)) {
        float acc_pl = 0.f;
#pragma unroll
        for (int rj = 0; rj < 4; ++rj) {
            float cnt = ldcg(&g_counts[tid + rj * NTHR]);
            float p = cnt * (1.f / 65536.f);
            acc_pl += p * logf(p + 1e-10f);
        }
        s_part[tid] = acc_pl;
        __syncthreads();
        for (int off = 128; off > 0; off >>= 1) {
            if (tid < off) s_part[tid] += s_part[tid + off];
            __syncthreads();
        }
        if (tid == 0) {
            float ls = ldcg(&g_loss_sum);
            out[0]       = 1.25f * ls * (1.f / (float)(N_TOKENS * DIM));
            out[OFF_PPL] = expf(-s_part[0]);
            g_loss_sum = 0.f;
            g_ticket   = 0u;
        }
#pragma unroll
        for (int rj = 0; rj < 4; ++rj) g_counts[tid + rj * NTHR] = 0.f;
    }
}

// ---------------------------------------------------------------------------
extern "C" void kernel_launch(void* const* d_in, const int* in_sizes, int n_in,
                              void* d_out, int out_size) {
    const float* inputs = (const float*)d_in[0];   // [64,32,32,64] fp32
    const float* weight = (const float*)d_in[1];   // [1024,64] fp32
    float* out = (float*)d_out;

    cudaFuncSetAttribute(k_main, cudaFuncAttributeMaxDynamicSharedMemorySize, SM_TOTAL);
    k_prep<<<8, 128>>>(weight);
    k_main<<<N_TOKENS / BM, NTHR, SM_TOTAL>>>(inputs, weight, out);
}

// round 10
// speedup vs baseline: 1.0144x; 1.0144x over previous
#include <cuda_runtime.h>
#include <cuda_bf16.h>
#include <cstdint>

// Problem constants
#define NUM_EMB   1024
#define DIM       64
#define N_TOKENS  65536
#define BM        128          // tokens per CTA
#define BN        128          // codes per chunk
#define NCH       8            // 1024/128
#define PAD       68
#define NTHR      256          // 8 warps

// Output layout (single fp32 buffer)
#define OFF_Q     1
#define OFF_PPL   (1 + N_TOKENS*DIM)
#define OFF_IDX   (2 + N_TOKENS*DIM)

typedef unsigned long long ull;

// Device state
__device__ __nv_bfloat16 g_wsp[NUM_EMB * 128];  // per code: [e1(64) | e2(64)]
__device__ float    g_ensq[NUM_EMB];
__device__ float    g_counts[NUM_EMB];
__device__ float    g_loss_sum;
__device__ unsigned g_ticket;

// ---------------------------------------------------------------------------
// smem layout (bytes)
#define SM_AB     0                        // bf16 [x1|x2]: 128*256 = 32768
#define SM_B      32768                    // 2 bufs * 128*256 = 65536
#define SM_EN     98304                    // 1024 floats (biased +1) = 4096
#define SM_XSQ    102400                   // 128 floats -> 512
#define SM_IDX    102912                   // 128 ints -> 512
#define SM_PART   103424                   // 256 floats = 1024
#define SM_TICK   104448
#define SM_TOTAL  104464

// ---------------------------------------------------------------------------
#define LDSM_X4(r0,r1,r2,r3,addr) \
  asm volatile("ldmatrix.sync.aligned.m8n8.x4.shared.b16 {%0,%1,%2,%3}, [%4];" \
    : "=r"(r0),"=r"(r1),"=r"(r2),"=r"(r3) : "r"(addr))

#define MMA16816(d,a,b0,b1) \
  asm volatile("mma.sync.aligned.m16n8k16.row.col.f32.bf16.bf16.f32 " \
    "{%0,%1,%2,%3},{%4,%5,%6,%7},{%8,%9},{%0,%1,%2,%3};" \
    : "+f"((d)[0]),"+f"((d)[1]),"+f"((d)[2]),"+f"((d)[3]) \
    : "r"((a)[0]),"r"((a)[1]),"r"((a)[2]),"r"((a)[3]),"r"(b0),"r"(b1))

__device__ __forceinline__ void cp16(unsigned saddr, const void* gaddr) {
    asm volatile("cp.async.cg.shared.global [%0], [%1], 16;" :: "r"(saddr), "l"(gaddr));
}
#define CP_COMMIT() asm volatile("cp.async.commit_group;" ::: "memory")
#define CP_WAIT1()  asm volatile("cp.async.wait_group 1;" ::: "memory")
#define CP_WAIT0()  asm volatile("cp.async.wait_group 0;" ::: "memory")
__device__ __forceinline__ float ldcg(const float* p) {
    float v; asm volatile("ld.global.cg.f32 %0, [%1];" : "=f"(v) : "l"(p)); return v;
}

// top-3 key insert (smaller key = better (metric, idx))
__device__ __forceinline__ void ins3(ull& t0, ull& t1, ull& t2, ull k) {
    if (k < t2) {
        if (k < t0)      { t2 = t1; t1 = t0; t0 = k; }
        else if (k < t1) { t2 = t1; t1 = k; }
        else               t2 = k;
    }
}
__device__ __forceinline__ ull mkkey(float s, int idx) {
    return ((ull)__float_as_uint(s) << 10) | (unsigned)idx;
}
__device__ __forceinline__ float keysc(ull k) {
    return __uint_as_float((unsigned)(k >> 10));
}

// ---------------------------------------------------------------------------
// k_prep: W exact 2-way bf16 split + code norms (sequential unfused = ref)
// ---------------------------------------------------------------------------
__global__ void k_prep(const float* __restrict__ weight) {
    __shared__ float sw[128 * PAD];
    const int tid = threadIdx.x;             // 128
    const int b   = blockIdx.x;              // 8
    const float* g = weight + (size_t)b * 128 * DIM;
#pragma unroll
    for (int i = 0; i < 64; ++i) {
        int e = tid + i * 128;
        sw[(e >> 6) * PAD + (e & 63)] = g[e];
    }
    __syncthreads();
    const int k = b * 128 + tid;
    const float* x = sw + tid * PAD;
    float s = 0.f;
#pragma unroll
    for (int d = 0; d < DIM; ++d) {
        float v = x[d];
        s = __fadd_rn(s, __fmul_rn(v, v));
        __nv_bfloat16 e1 = __float2bfloat16_rn(v);
        float r1 = v - __bfloat162float(e1);
        __nv_bfloat16 e2 = __float2bfloat16_rn(r1);
        g_wsp[(size_t)k * 128 + d]      = e1;
        g_wsp[(size_t)k * 128 + 64 + d] = e2;
    }
    g_ensq[k] = s;
}

// ---------------------------------------------------------------------------
// MMA tile: chain X = x1.e1 + x1.e2 (8 dep MMAs), chain Y = x2.e1 (4 MMAs),
// two n8 columns (A, B). Accumulators zeroed at entry.
// ---------------------------------------------------------------------------
__device__ __forceinline__ void mma_step(
    uint32_t bbuf, int n0a,
    const uint32_t (&afr)[8][4], const uint32_t (&boff)[4],
    float (&XA)[4], float (&YA)[4], float (&XB)[4], float (&YB)[4])
{
#pragma unroll
    for (int i = 0; i < 4; ++i) { XA[i] = 0.f; YA[i] = 0.f; XB[i] = 0.f; YB[i] = 0.f; }
    uint32_t fa[8], fb[8];
    const uint32_t rA = bbuf + n0a * 256;
    const uint32_t rB = rA + 2048;
    // e1 fragments
    LDSM_X4(fa[0],fa[1],fa[2],fa[3], rA + boff[0]);
    LDSM_X4(fa[4],fa[5],fa[6],fa[7], rA + boff[1]);
    LDSM_X4(fb[0],fb[1],fb[2],fb[3], rB + boff[0]);
    LDSM_X4(fb[4],fb[5],fb[6],fb[7], rB + boff[1]);
#pragma unroll
    for (int j = 0; j < 4; ++j) {
        MMA16816(XA, afr[j],   fa[2*j], fa[2*j+1]);
        MMA16816(XB, afr[j],   fb[2*j], fb[2*j+1]);
        MMA16816(YA, afr[4+j], fa[2*j], fa[2*j+1]);
        MMA16816(YB, afr[4+j], fb[2*j], fb[2*j+1]);
    }
    // e2 fragments (reuse regs) -> continue chain X
    LDSM_X4(fa[0],fa[1],fa[2],fa[3], rA + boff[2]);
    LDSM_X4(fa[4],fa[5],fa[6],fa[7], rA + boff[3]);
    LDSM_X4(fb[0],fb[1],fb[2],fb[3], rB + boff[2]);
    LDSM_X4(fb[4],fb[5],fb[6],fb[7], rB + boff[3]);
#pragma unroll
    for (int j = 0; j < 4; ++j) {
        MMA16816(XA, afr[j], fa[2*j], fa[2*j+1]);
        MMA16816(XB, afr[j], fb[2*j], fb[2*j+1]);
    }
}

// deferred scoring of a completed tile (colB < 0 -> nothing pending)
#define SCORE_STEP(XA, YA, XB, YB, colB) do {                                  \
    if ((colB) >= 0) {                                                         \
        float2 enA = enp[(colB) >> 1];                                         \
        float2 enB = enp[((colB) >> 1) + 4];                                   \
        float sA0 = fmaf(-2.f, XA[0] + YA[0], enA.x);                          \
        float sA1 = fmaf(-2.f, XA[1] + YA[1], enA.y);                          \
        float sA2 = fmaf(-2.f, XA[2] + YA[2], enA.x);                          \
        float sA3 = fmaf(-2.f, XA[3] + YA[3], enA.y);                          \
        float sB0 = fmaf(-2.f, XB[0] + YB[0], enB.x);                          \
        float sB1 = fmaf(-2.f, XB[1] + YB[1], enB.y);                          \
        float sB2 = fmaf(-2.f, XB[2] + YB[2], enB.x);                          \
        float sB3 = fmaf(-2.f, XB[3] + YB[3], enB.y);                          \
        float mLo = fminf(fminf(sA0, sA1), fminf(sB0, sB1));                   \
        float mHi = fminf(fminf(sA2, sA3), fminf(sB2, sB3));                   \
        if (mLo <= t2Lo) {                                                     \
            ins3(kLo0, kLo1, kLo2, mkkey(sA0, (colB)));                        \
            ins3(kLo0, kLo1, kLo2, mkkey(sA1, (colB) + 1));                    \
            ins3(kLo0, kLo1, kLo2, mkkey(sB0, (colB) + 8));                    \
            ins3(kLo0, kLo1, kLo2, mkkey(sB1, (colB) + 9));                    \
            t2Lo = keysc(kLo2);                                                \
        }                                                                      \
        if (mHi <= t2Hi) {                                                     \
            ins3(kHi0, kHi1, kHi2, mkkey(sA2, (colB)));                        \
            ins3(kHi0, kHi1, kHi2, mkkey(sA3, (colB) + 1));                    \
            ins3(kHi0, kHi1, kHi2, mkkey(sB2, (colB) + 8));                    \
            ins3(kHi0, kHi1, kHi2, mkkey(sB3, (colB) + 9));                    \
            t2Hi = keysc(kHi2);                                                \
        }                                                                      \
    }                                                                          \
} while (0)

// ---------------------------------------------------------------------------
// k_main: 3-term bf16-split mma.sync pruning GEMM (software-pipelined scoring)
//         + exact-rescore argmin + fused epilogue
// ---------------------------------------------------------------------------
__global__ __launch_bounds__(NTHR, 2)
void k_main(const float* __restrict__ inputs,
            const float* __restrict__ weight,
            float* __restrict__ out) {
    extern __shared__ char smem[];
    float* s_en  = (float*)(smem + SM_EN);    // 1 + ensq (biased)
    float* s_xsq = (float*)(smem + SM_XSQ);
    int*   s_idx = (int*)  (smem + SM_IDX);
    float* s_part= (float*)(smem + SM_PART);
    unsigned* s_tick = (unsigned*)(smem + SM_TICK);

    const uint32_t sbase = (uint32_t)__cvta_generic_to_shared(smem);
    const int tid  = threadIdx.x;
    const int w    = tid >> 5;
    const int lane = tid & 31;
    const int tok0 = blockIdx.x * BM;

    // --- prefetch B chunk 0: [e1|e2] rows (256B), SW swizzled ---
#pragma unroll
    for (int it = 0; it < 8; ++it) {
        int e = tid + it * NTHR;             // 0..2047
        int row = e >> 4, g = e & 15;
        uint32_t dst = sbase + SM_B + row * 256 + ((g >> 3) << 7)
                     + ((((g & 7) ^ (row & 7)) << 4));
        cp16(dst, g_wsp + ((size_t)row << 7) + g * 8);
    }
    CP_COMMIT();

    // --- biased code norms (1 + ensq) ---
#pragma unroll
    for (int it = 0; it < 4; ++it) {
        int e = tid + it * NTHR;
        s_en[e] = 1.0f + g_ensq[e];
    }

    // --- A exact 2-way bf16 split (d-pairs, packed STS.32) ---
    {
        const float2* gx2 = (const float2*)(inputs + (size_t)tok0 * DIM);
#pragma unroll
        for (int it = 0; it < 16; ++it) {
            int e = tid + it * NTHR;         // 0..4095 pairs
            int row = e >> 5, p = e & 31;
            int d = p * 2;
            float2 v = __ldg(gx2 + e);
            __nv_bfloat16 x1a = __float2bfloat16_rn(v.x);
            __nv_bfloat16 x1b = __float2bfloat16_rn(v.y);
            float r1a = v.x - __bfloat162float(x1a);
            float r1b = v.y - __bfloat162float(x1b);
            __nv_bfloat16 x2a = __float2bfloat16_rn(r1a);
            __nv_bfloat16 x2b = __float2bfloat16_rn(r1b);
            uint32_t p1 = (uint32_t)*(uint16_t*)&x1a | ((uint32_t)*(uint16_t*)&x1b << 16);
            uint32_t p2 = (uint32_t)*(uint16_t*)&x2a | ((uint32_t)*(uint16_t*)&x2b << 16);
            uint32_t sw = (uint32_t)((((d >> 3) & 7) ^ (row & 7)) << 4)
                        | (uint32_t)((d * 2) & 15);
            *(uint32_t*)(smem + SM_AB + row * 256 + sw)       = p1;
            *(uint32_t*)(smem + SM_AB + row * 256 + 128 + sw) = p2;
        }
    }

    // --- ||x||^2: sequential UNFUSED (replicates reference rounding) ---
    if (tid < BM) {
        const float* x = inputs + (size_t)(tok0 + tid) * DIM;
        float s = 0.f;
#pragma unroll
        for (int d = 0; d < DIM; ++d) {
            float v = __ldg(x + d);
            s = __fadd_rn(s, __fmul_rn(v, v));
        }
        s_xsq[tid] = s;
    }
    __syncthreads();

    // --- per-warp A fragments in registers: m16 x k128 ([x1|x2]) ---
    uint32_t afr[8][4];
    {
        const int tr = lane & 15;
        const int kadd = (lane >> 4) * 16;
#pragma unroll
        for (int u = 0; u < 8; ++u) {
            int kb = u * 32 + kadd;
            uint32_t addr = sbase + SM_AB + (w * 16 + tr) * 256 + (kb & 128)
                          + (((((kb >> 4) & 7) ^ (tr & 7)) << 4));
            LDSM_X4(afr[u][0], afr[u][1], afr[u][2], afr[u][3], addr);
        }
    }

    // --- B lane address offsets (i=0,1 -> e1; i=2,3 -> e2) ---
    const int cr = lane & 7;
    const int klane = (lane >> 3) & 3;
    uint32_t boff[4];
#pragma unroll
    for (int i = 0; i < 4; ++i) {
        int kb = i * 64 + klane * 16;
        boff[i] = (uint32_t)(cr * 256 + (kb & 128)
                + (((((kb >> 4) & 7) ^ cr) << 4)));
    }

    const float xq_lo = s_xsq[w * 16 + (lane >> 2)];
    const float xq_hi = s_xsq[w * 16 + (lane >> 2) + 8];
    ull kLo0 = mkkey(3.4e38f, 1023), kLo1 = kLo0, kLo2 = kLo0;
    ull kHi0 = kLo0,                 kHi1 = kLo0, kHi2 = kLo0;
    float t2Lo = 3.4e38f, t2Hi = 3.4e38f;

    const float2* enp = (const float2*)s_en;
    const int enl = lane & 3;

    // pipelined accumulator sets
    float X0A[4], Y0A[4], X0B[4], Y0B[4];
    float X1A[4], Y1A[4], X1B[4], Y1B[4];
    int pcol0 = -1, pcol1 = -1;

#pragma unroll 1
    for (int c = 0; c < NCH; ++c) {
        if (c + 1 < NCH) {
            const uint32_t dst0 = sbase + SM_B + ((c + 1) & 1) * 32768;
            const size_t srow = (size_t)(c + 1) * BN;
#pragma unroll
            for (int it = 0; it < 8; ++it) {
                int e = tid + it * NTHR;
                int row = e >> 4, g = e & 15;
                uint32_t dst = dst0 + row * 256 + ((g >> 3) << 7)
                             + ((((g & 7) ^ (row & 7)) << 4));
                cp16(dst, g_wsp + ((srow + row) << 7) + g * 8);
            }
            CP_COMMIT();
            CP_WAIT1();
        } else {
            CP_COMMIT();
            CP_WAIT0();
        }
        __syncthreads();

        const uint32_t bbuf = sbase + SM_B + (c & 1) * 32768;
        const int cbase = c * BN + enl * 2;

#pragma unroll
        for (int h = 0; h < 4; ++h) {
            // tile 2h -> set0; score set1 (previous tile) in its shadow
            mma_step(bbuf, h * 32, afr, boff, X0A, Y0A, X0B, Y0B);
            SCORE_STEP(X1A, Y1A, X1B, Y1B, pcol1);
            pcol0 = cbase + h * 32;
            // tile 2h+1 -> set1; score set0 in its shadow
            mma_step(bbuf, h * 32 + 16, afr, boff, X1A, Y1A, X1B, Y1B);
            SCORE_STEP(X0A, Y0A, X0B, Y0B, pcol0);
            pcol1 = cbase + h * 32 + 16;
        }
        __syncthreads();
    }
    // drain the final pending tile
    SCORE_STEP(X1A, Y1A, X1B, Y1B, pcol1);

    // --- winner resolution: window filter + exact (round-1) rescore ---
#pragma unroll
    for (int half = 0; half < 2; ++half) {
        ull k0 = half ? kHi0 : kLo0;
        ull k1 = half ? kHi1 : kLo1;
        ull k2 = half ? kHi2 : kLo2;
        float xq = half ? xq_hi : xq_lo;
        int trow = w * 16 + (lane >> 2) + half * 8;

        ull m = k0, o;
        o = __shfl_xor_sync(0xffffffffu, m, 1); m = o < m ? o : m;
        o = __shfl_xor_sync(0xffffffffu, m, 2); m = o < m ? o : m;
        float win = keysc(m) + 2e-5f;

        float s0f = keysc(k0), s1f = keysc(k1), s2f = keysc(k2);
        int cnt = (int)(s0f <= win) + (int)(s1f <= win) + (int)(s2f <= win);
        cnt += __shfl_xor_sync(0xffffffffu, cnt, 1);
        cnt += __shfl_xor_sync(0xffffffffu, cnt, 2);

        ull ebest = ~0ull;
        if (cnt > 1) {
            const float* xrow = inputs + (size_t)(tok0 + trow) * DIM;
            ull   ks[3] = {k0, k1, k2};
            float sf[3] = {s0f, s1f, s2f};
#pragma unroll 1
            for (int j = 0; j < 3; ++j) {
                if (sf[j] <= win) {
                    int idx = (int)(ks[j] & 1023);
                    const float* wrow = weight + (size_t)idx * DIM;
                    float aLo = 0.f, aHi = 0.f;
#pragma unroll
                    for (int d = 0; d < 32; ++d) {
                        aLo = fmaf(__ldg(xrow + 2*d),     __ldg(wrow + 2*d),     aLo);
                        aHi = fmaf(__ldg(xrow + 2*d + 1), __ldg(wrow + 2*d + 1), aHi);
                    }
                    float dot = __fadd_rn(aLo, aHi);
                    float es = fmaf(-2.f, dot, __fadd_rn(xq, ldcg(&g_ensq[idx])));
                    ull ek = mkkey(es, idx);
                    if (ek < ebest) ebest = ek;
                }
            }
        }
        o = __shfl_xor_sync(0xffffffffu, ebest, 1); ebest = o < ebest ? o : ebest;
        o = __shfl_xor_sync(0xffffffffu, ebest, 2); ebest = o < ebest ? o : ebest;

        int widx = (cnt == 1) ? (int)(m & 1023) : (int)(ebest & 1023);
        if ((lane & 3) == 0) {
            s_idx[trow] = widx;
            out[OFF_IDX + (size_t)(tok0 + trow)] = (float)widx;
            atomicAdd(&g_counts[widx], 1.f);
        }
    }
    __syncthreads();

    // --- gather codes -> quantized output + loss partial (float4 loads) ---
    float local = 0.f;
    {
        const float4* gx4 = (const float4*)(inputs + (size_t)tok0 * DIM);
#pragma unroll
        for (int it = 0; it < 8; ++it) {
            int t  = it * 16 + (tid >> 4);   // token 0..127
            int dq = tid & 15;               // float4 lane 0..15
            float4 qv = __ldg((const float4*)(weight + (size_t)s_idx[t] * DIM) + dq);
            float4 xv = __ldg(gx4 + t * 16 + dq);
            size_t ob = OFF_Q + (size_t)(tok0 + t) * DIM + dq * 4;
            out[ob]     = qv.x;
            out[ob + 1] = qv.y;
            out[ob + 2] = qv.z;
            out[ob + 3] = qv.w;
            float da = qv.x - xv.x, db = qv.y - xv.y;
            float dc = qv.z - xv.z, dd = qv.w - xv.w;
            local = fmaf(da, da, local);
            local = fmaf(db, db, local);
            local = fmaf(dc, dc, local);
            local = fmaf(dd, dd, local);
        }
    }
    s_part[tid] = local;
    __syncthreads();
    for (int off = 128; off > 0; off >>= 1) {
        if (tid < off) s_part[tid] += s_part[tid + off];
        __syncthreads();
    }
    if (tid == 0) atomicAdd(&g_loss_sum, s_part[0]);

    // --- last-block finalization (ticket) ---
    __threadfence();
    if (tid == 0) *s_tick = atomicAdd(&g_ticket, 1u);
    __syncthreads();
    if (*s_tick == (unsigned)(gridDim.x - 1)) {
        float acc_pl = 0.f;
#pragma unroll
        for (int rj = 0; rj < 4; ++rj) {
            float cnt = ldcg(&g_counts[tid + rj * NTHR]);
            float p = cnt * (1.f / 65536.f);
            acc_pl += p * logf(p + 1e-10f);
        }
        s_part[tid] = acc_pl;
        __syncthreads();
        for (int off = 128; off > 0; off >>= 1) {
            if (tid < off) s_part[tid] += s_part[tid + off];
            __syncthreads();
        }
        if (tid == 0) {
            float ls = ldcg(&g_loss_sum);
            out[0]       = 1.25f * ls * (1.f / (float)(N_TOKENS * DIM));
            out[OFF_PPL] = expf(-s_part[0]);
            g_loss_sum = 0.f;
            g_ticket   = 0u;
        }
#pragma unroll
        for (int rj = 0; rj < 4; ++rj) g_counts[tid + rj * NTHR] = 0.f;
    }
}

// ---------------------------------------------------------------------------
extern "C" void kernel_launch(void* const* d_in, const int* in_sizes, int n_in,
                              void* d_out, int out_size) {
    const float* inputs = (const float*)d_in[0];   // [64,32,32,64] fp32
    const float* weight = (const float*)d_in[1];   // [1024,64] fp32
    float* out = (float*)d_out;

    cudaFuncSetAttribute(k_main, cudaFuncAttributeMaxDynamicSharedMemorySize, SM_TOTAL);
    k_prep<<<8, 128>>>(weight);
    k_main<<<N_TOKENS / BM, NTHR, SM_TOTAL>>>(inputs, weight, out);
}

// round 11
// speedup vs baseline: 1.1508x; 1.1344x over previous
#include <cuda_runtime.h>
#include <cuda_bf16.h>
#include <cstdint>

// Problem constants
#define NUM_EMB   1024
#define DIM       64
#define N_TOKENS  65536
#define BM        128          // tokens per CTA
#define BN        128          // codes per chunk
#define NCH       8            // 1024/128
#define PAD       68
#define NTHR      256          // 8 warps

// Output layout (single fp32 buffer)
#define OFF_Q     1
#define OFF_PPL   (1 + N_TOKENS*DIM)
#define OFF_IDX   (2 + N_TOKENS*DIM)

typedef unsigned long long ull;

// Device state
__device__ __nv_bfloat16 g_wsp[NUM_EMB * 128];  // per code: [e1(64) | e2(64)]
__device__ float    g_ensq[NUM_EMB];
__device__ float    g_counts[NUM_EMB];
__device__ float    g_loss_sum;
__device__ unsigned g_ticket;

// ---------------------------------------------------------------------------
// smem layout (bytes)
#define SM_AB     0                        // bf16 [x1|x2]: 128*256 = 32768
#define SM_B      32768                    // 2 bufs * 128*256 = 65536
#define SM_EN     98304                    // 1024 floats (biased +1) = 4096
#define SM_XSQ    102400                   // 128 floats -> 512
#define SM_IDX    102912                   // 128 ints -> 512
#define SM_PART   103424                   // 256 floats = 1024
#define SM_TICK   104448
#define SM_TOTAL  104464

// ---------------------------------------------------------------------------
#define LDSM_X4(r0,r1,r2,r3,addr) \
  asm volatile("ldmatrix.sync.aligned.m8n8.x4.shared.b16 {%0,%1,%2,%3}, [%4];" \
    : "=r"(r0),"=r"(r1),"=r"(r2),"=r"(r3) : "r"(addr))

#define MMA16816(d,a,b0,b1) \
  asm volatile("mma.sync.aligned.m16n8k16.row.col.f32.bf16.bf16.f32 " \
    "{%0,%1,%2,%3},{%4,%5,%6,%7},{%8,%9},{%0,%1,%2,%3};" \
    : "+f"((d)[0]),"+f"((d)[1]),"+f"((d)[2]),"+f"((d)[3]) \
    : "r"((a)[0]),"r"((a)[1]),"r"((a)[2]),"r"((a)[3]),"r"(b0),"r"(b1))

// first MMA of a chain: D = A*B + 0 (no accumulator zeroing MOVs)
#define MMA16816_Z(d,a,b0,b1,z) \
  asm volatile("mma.sync.aligned.m16n8k16.row.col.f32.bf16.bf16.f32 " \
    "{%0,%1,%2,%3},{%4,%5,%6,%7},{%8,%9},{%10,%10,%10,%10};" \
    : "=f"((d)[0]),"=f"((d)[1]),"=f"((d)[2]),"=f"((d)[3]) \
    : "r"((a)[0]),"r"((a)[1]),"r"((a)[2]),"r"((a)[3]),"r"(b0),"r"(b1),"f"(z))

__device__ __forceinline__ void cp16(unsigned saddr, const void* gaddr) {
    asm volatile("cp.async.cg.shared.global [%0], [%1], 16;" :: "r"(saddr), "l"(gaddr));
}
#define CP_COMMIT() asm volatile("cp.async.commit_group;" ::: "memory")
#define CP_WAIT1()  asm volatile("cp.async.wait_group 1;" ::: "memory")
#define CP_WAIT0()  asm volatile("cp.async.wait_group 0;" ::: "memory")
__device__ __forceinline__ float ldcg(const float* p) {
    float v; asm volatile("ld.global.cg.f32 %0, [%1];" : "=f"(v) : "l"(p)); return v;
}

// top-3 key insert (smaller key = better (metric, idx))
__device__ __forceinline__ void ins3(ull& t0, ull& t1, ull& t2, ull k) {
    if (k < t2) {
        if (k < t0)      { t2 = t1; t1 = t0; t0 = k; }
        else if (k < t1) { t2 = t1; t1 = k; }
        else               t2 = k;
    }
}
__device__ __forceinline__ ull mkkey(float s, int idx) {
    return ((ull)__float_as_uint(s) << 10) | (unsigned)idx;
}
__device__ __forceinline__ float keysc(ull k) {
    return __uint_as_float((unsigned)(k >> 10));
}

// ---------------------------------------------------------------------------
// k_prep: W exact 2-way bf16 split (coalesced packed stores) + code norms
// (sequential unfused = reference order). 16 blocks x 256 threads.
// ---------------------------------------------------------------------------
__global__ void k_prep(const float* __restrict__ weight) {
    __shared__ float sw[64 * PAD];
    const int tid = threadIdx.x;             // 256
    const int b   = blockIdx.x;              // 16 -> 64 codes each
    const float* g = weight + (size_t)b * 64 * DIM;
#pragma unroll
    for (int i = 0; i < 16; ++i) {           // stage 64x64 floats coalesced
        int e = tid + i * 256;
        sw[(e >> 6) * PAD + (e & 63)] = g[e];
    }
    __syncthreads();
    // ensq: one thread per code, sequential UNFUSED (= reference rounding)
    if (tid < 64) {
        const float* x = sw + tid * PAD;
        float s = 0.f;
#pragma unroll
        for (int d = 0; d < DIM; ++d) {
            float v = x[d];
            s = __fadd_rn(s, __fmul_rn(v, v));
        }
        g_ensq[b * 64 + tid] = s;
    }
    // split: pairs, packed u32 stores, coalesced (warp covers one code row)
    uint32_t* w1 = (uint32_t*)g_wsp;         // code row = 64 u32: [e1(32)|e2(32)]
#pragma unroll
    for (int i = 0; i < 8; ++i) {
        int p = tid + i * 256;               // 0..2047 pairs
        int code = p >> 5, dp = p & 31;
        float v0 = sw[code * PAD + dp * 2];
        float v1 = sw[code * PAD + dp * 2 + 1];
        __nv_bfloat16 a1 = __float2bfloat16_rn(v0);
        __nv_bfloat16 b1 = __float2bfloat16_rn(v1);
        float r0 = v0 - __bfloat162float(a1);
        float r1 = v1 - __bfloat162float(b1);
        __nv_bfloat16 a2 = __float2bfloat16_rn(r0);
        __nv_bfloat16 b2 = __float2bfloat16_rn(r1);
        uint32_t p1 = (uint32_t)*(uint16_t*)&a1 | ((uint32_t)*(uint16_t*)&b1 << 16);
        uint32_t p2 = (uint32_t)*(uint16_t*)&a2 | ((uint32_t)*(uint16_t*)&b2 << 16);
        size_t row = (size_t)(b * 64 + code) * 64;
        w1[row + dp]      = p1;
        w1[row + 32 + dp] = p2;
    }
}

// ---------------------------------------------------------------------------
// MMA tile: single 12-MMA chain per column (x1.e1 + x1.e2 + x2.e1),
// zero-C first MMA, all 16 LDSM issued upfront.
// ---------------------------------------------------------------------------
__device__ __forceinline__ void mma_step(
    uint32_t bbuf, int n0a,
    const uint32_t (&afr)[8][4], const uint32_t (&boff)[4],
    float (&DA)[4], float (&DB)[4])
{
    uint32_t fa[16], fb[16];
    const uint32_t rA = bbuf + n0a * 256;
    const uint32_t rB = rA + 2048;
    LDSM_X4(fa[0], fa[1], fa[2], fa[3],  rA + boff[0]);   // e1 k0-63
    LDSM_X4(fa[4], fa[5], fa[6], fa[7],  rA + boff[1]);   // e1 k64-127
    LDSM_X4(fa[8], fa[9], fa[10],fa[11], rA + boff[2]);   // e2 k0-63
    LDSM_X4(fa[12],fa[13],fa[14],fa[15], rA + boff[3]);   // e2 k64-127
    LDSM_X4(fb[0], fb[1], fb[2], fb[3],  rB + boff[0]);
    LDSM_X4(fb[4], fb[5], fb[6], fb[7],  rB + boff[1]);
    LDSM_X4(fb[8], fb[9], fb[10],fb[11], rB + boff[2]);
    LDSM_X4(fb[12],fb[13],fb[14],fb[15], rB + boff[3]);

    MMA16816_Z(DA, afr[0], fa[0], fa[1], 0.f);            // x1.e1 (start)
    MMA16816_Z(DB, afr[0], fb[0], fb[1], 0.f);
#pragma unroll
    for (int j = 1; j < 4; ++j) {
        MMA16816(DA, afr[j], fa[2*j], fa[2*j+1]);
        MMA16816(DB, afr[j], fb[2*j], fb[2*j+1]);
    }
#pragma unroll
    for (int j = 0; j < 4; ++j) {                          // x1.e2
        MMA16816(DA, afr[j], fa[8+2*j], fa[8+2*j+1]);
        MMA16816(DB, afr[j], fb[8+2*j], fb[8+2*j+1]);
    }
#pragma unroll
    for (int j = 0; j < 4; ++j) {                          // x2.e1
        MMA16816(DA, afr[4+j], fa[2*j], fa[2*j+1]);
        MMA16816(DB, afr[4+j], fb[2*j], fb[2*j+1]);
    }
}

// deferred scoring of a completed tile (colB < 0 -> nothing pending)
#define SCORE_STEP(DA, DB, colB) do {                                          \
    if ((colB) >= 0) {                                                         \
        float2 enA = enp[(colB) >> 1];                                         \
        float2 enB = enp[((colB) >> 1) + 4];                                   \
        float sA0 = fmaf(-2.f, DA[0], enA.x);                                  \
        float sA1 = fmaf(-2.f, DA[1], enA.y);                                  \
        float sA2 = fmaf(-2.f, DA[2], enA.x);                                  \
        float sA3 = fmaf(-2.f, DA[3], enA.y);                                  \
        float sB0 = fmaf(-2.f, DB[0], enB.x);                                  \
        float sB1 = fmaf(-2.f, DB[1], enB.y);                                  \
        float sB2 = fmaf(-2.f, DB[2], enB.x);                                  \
        float sB3 = fmaf(-2.f, DB[3], enB.y);                                  \
        float mLo = fminf(fminf(sA0, sA1), fminf(sB0, sB1));                   \
        float mHi = fminf(fminf(sA2, sA3), fminf(sB2, sB3));                   \
        if (mLo <= t2Lo) {                                                     \
            ins3(kLo0, kLo1, kLo2, mkkey(sA0, (colB)));                        \
            ins3(kLo0, kLo1, kLo2, mkkey(sA1, (colB) + 1));                    \
            ins3(kLo0, kLo1, kLo2, mkkey(sB0, (colB) + 8));                    \
            ins3(kLo0, kLo1, kLo2, mkkey(sB1, (colB) + 9));                    \
            t2Lo = keysc(kLo2);                                                \
        }                                                                      \
        if (mHi <= t2Hi) {                                                     \
            ins3(kHi0, kHi1, kHi2, mkkey(sA2, (colB)));                        \
            ins3(kHi0, kHi1, kHi2, mkkey(sA3, (colB) + 1));                    \
            ins3(kHi0, kHi1, kHi2, mkkey(sB2, (colB) + 8));                    \
            ins3(kHi0, kHi1, kHi2, mkkey(sB3, (colB) + 9));                    \
            t2Hi = keysc(kHi2);                                                \
        }                                                                      \
    }                                                                          \
} while (0)

// ---------------------------------------------------------------------------
// k_main: 3-term bf16-split mma.sync pruning GEMM (pipelined scoring)
//         + exact-rescore argmin + fused epilogue
// ---------------------------------------------------------------------------
__global__ __launch_bounds__(NTHR, 2)
void k_main(const float* __restrict__ inputs,
            const float* __restrict__ weight,
            float* __restrict__ out) {
    extern __shared__ char smem[];
    float* s_en  = (float*)(smem + SM_EN);    // 1 + ensq (biased)
    float* s_xsq = (float*)(smem + SM_XSQ);
    int*   s_idx = (int*)  (smem + SM_IDX);
    float* s_part= (float*)(smem + SM_PART);
    unsigned* s_tick = (unsigned*)(smem + SM_TICK);

    const uint32_t sbase = (uint32_t)__cvta_generic_to_shared(smem);
    const int tid  = threadIdx.x;
    const int w    = tid >> 5;
    const int lane = tid & 31;
    const int tok0 = blockIdx.x * BM;

    // --- prefetch B chunk 0: [e1|e2] rows (256B), SW swizzled ---
#pragma unroll
    for (int it = 0; it < 8; ++it) {
        int e = tid + it * NTHR;             // 0..2047
        int row = e >> 4, g = e & 15;
        uint32_t dst = sbase + SM_B + row * 256 + ((g >> 3) << 7)
                     + ((((g & 7) ^ (row & 7)) << 4));
        cp16(dst, g_wsp + ((size_t)row << 7) + g * 8);
    }
    CP_COMMIT();

    // --- biased code norms (1 + ensq) ---
#pragma unroll
    for (int it = 0; it < 4; ++it) {
        int e = tid + it * NTHR;
        s_en[e] = 1.0f + g_ensq[e];
    }

    // --- A exact 2-way bf16 split (d-pairs, packed STS.32) ---
    {
        const float2* gx2 = (const float2*)(inputs + (size_t)tok0 * DIM);
#pragma unroll
        for (int it = 0; it < 16; ++it) {
            int e = tid + it * NTHR;         // 0..4095 pairs
            int row = e >> 5, p = e & 31;
            int d = p * 2;
            float2 v = __ldg(gx2 + e);
            __nv_bfloat16 x1a = __float2bfloat16_rn(v.x);
            __nv_bfloat16 x1b = __float2bfloat16_rn(v.y);
            float r1a = v.x - __bfloat162float(x1a);
            float r1b = v.y - __bfloat162float(x1b);
            __nv_bfloat16 x2a = __float2bfloat16_rn(r1a);
            __nv_bfloat16 x2b = __float2bfloat16_rn(r1b);
            uint32_t p1 = (uint32_t)*(uint16_t*)&x1a | ((uint32_t)*(uint16_t*)&x1b << 16);
            uint32_t p2 = (uint32_t)*(uint16_t*)&x2a | ((uint32_t)*(uint16_t*)&x2b << 16);
            uint32_t sw = (uint32_t)((((d >> 3) & 7) ^ (row & 7)) << 4)
                        | (uint32_t)((d * 2) & 15);
            *(uint32_t*)(smem + SM_AB + row * 256 + sw)       = p1;
            *(uint32_t*)(smem + SM_AB + row * 256 + 128 + sw) = p2;
        }
    }

    // --- ||x||^2: sequential UNFUSED (replicates reference rounding) ---
    if (tid < BM) {
        const float* x = inputs + (size_t)(tok0 + tid) * DIM;
        float s = 0.f;
#pragma unroll
        for (int d = 0; d < DIM; ++d) {
            float v = __ldg(x + d);
            s = __fadd_rn(s, __fmul_rn(v, v));
        }
        s_xsq[tid] = s;
    }
    __syncthreads();

    // --- per-warp A fragments in registers: m16 x k128 ([x1|x2]) ---
    uint32_t afr[8][4];
    {
        const int tr = lane & 15;
        const int kadd = (lane >> 4) * 16;
#pragma unroll
        for (int u = 0; u < 8; ++u) {
            int kb = u * 32 + kadd;
            uint32_t addr = sbase + SM_AB + (w * 16 + tr) * 256 + (kb & 128)
                          + (((((kb >> 4) & 7) ^ (tr & 7)) << 4));
            LDSM_X4(afr[u][0], afr[u][1], afr[u][2], afr[u][3], addr);
        }
    }

    // --- B lane address offsets (i=0,1 -> e1; i=2,3 -> e2) ---
    const int cr = lane & 7;
    const int klane = (lane >> 3) & 3;
    uint32_t boff[4];
#pragma unroll
    for (int i = 0; i < 4; ++i) {
        int kb = i * 64 + klane * 16;
        boff[i] = (uint32_t)(cr * 256 + (kb & 128)
                + (((((kb >> 4) & 7) ^ cr) << 4)));
    }

    const float xq_lo = s_xsq[w * 16 + (lane >> 2)];
    const float xq_hi = s_xsq[w * 16 + (lane >> 2) + 8];
    ull kLo0 = mkkey(3.4e38f, 1023), kLo1 = kLo0, kLo2 = kLo0;
    ull kHi0 = kLo0,                 kHi1 = kLo0, kHi2 = kLo0;
    float t2Lo = 3.4e38f, t2Hi = 3.4e38f;

    const float2* enp = (const float2*)s_en;
    const int enl = lane & 3;

    // pipelined accumulator sets (8 regs each)
    float D0A[4], D0B[4], D1A[4], D1B[4];
    int pcol0 = -1, pcol1 = -1;

#pragma unroll 1
    for (int c = 0; c < NCH; ++c) {
        if (c + 1 < NCH) {
            const uint32_t dst0 = sbase + SM_B + ((c + 1) & 1) * 32768;
            const size_t srow = (size_t)(c + 1) * BN;
#pragma unroll
            for (int it = 0; it < 8; ++it) {
                int e = tid + it * NTHR;
                int row = e >> 4, g = e & 15;
                uint32_t dst = dst0 + row * 256 + ((g >> 3) << 7)
                             + ((((g & 7) ^ (row & 7)) << 4));
                cp16(dst, g_wsp + ((srow + row) << 7) + g * 8);
            }
            CP_COMMIT();
            CP_WAIT1();
        } else {
            CP_COMMIT();
            CP_WAIT0();
        }
        __syncthreads();

        const uint32_t bbuf = sbase + SM_B + (c & 1) * 32768;
        const int cbase = c * BN + enl * 2;

#pragma unroll
        for (int h = 0; h < 4; ++h) {
            // tile 2h -> set0; score set1 (previous tile) in its shadow
            mma_step(bbuf, h * 32, afr, boff, D0A, D0B);
            SCORE_STEP(D1A, D1B, pcol1);
            pcol0 = cbase + h * 32;
            // tile 2h+1 -> set1; score set0 in its shadow
            mma_step(bbuf, h * 32 + 16, afr, boff, D1A, D1B);
            SCORE_STEP(D0A, D0B, pcol0);
            pcol1 = cbase + h * 32 + 16;
        }
        __syncthreads();
    }
    // drain the final pending tile
    SCORE_STEP(D1A, D1B, pcol1);

    // --- winner resolution: window filter + exact (round-1) rescore ---
#pragma unroll
    for (int half = 0; half < 2; ++half) {
        ull k0 = half ? kHi0 : kLo0;
        ull k1 = half ? kHi1 : kLo1;
        ull k2 = half ? kHi2 : kLo2;
        float xq = half ? xq_hi : xq_lo;
        int trow = w * 16 + (lane >> 2) + half * 8;

        ull m = k0, o;
        o = __shfl_xor_sync(0xffffffffu, m, 1); m = o < m ? o : m;
        o = __shfl_xor_sync(0xffffffffu, m, 2); m = o < m ? o : m;
        float win = keysc(m) + 2e-5f;

        float s0f = keysc(k0), s1f = keysc(k1), s2f = keysc(k2);
        int cnt = (int)(s0f <= win) + (int)(s1f <= win) + (int)(s2f <= win);
        cnt += __shfl_xor_sync(0xffffffffu, cnt, 1);
        cnt += __shfl_xor_sync(0xffffffffu, cnt, 2);

        ull ebest = ~0ull;
        if (cnt > 1) {
            const float* xrow = inputs + (size_t)(tok0 + trow) * DIM;
            ull   ks[3] = {k0, k1, k2};
            float sf[3] = {s0f, s1f, s2f};
#pragma unroll 1
            for (int j = 0; j < 3; ++j) {
                if (sf[j] <= win) {
                    int idx = (int)(ks[j] & 1023);
                    const float* wrow = weight + (size_t)idx * DIM;
                    float aLo = 0.f, aHi = 0.f;
#pragma unroll
                    for (int d = 0; d < 32; ++d) {
                        aLo = fmaf(__ldg(xrow + 2*d),     __ldg(wrow + 2*d),     aLo);
                        aHi = fmaf(__ldg(xrow + 2*d + 1), __ldg(wrow + 2*d + 1), aHi);
                    }
                    float dot = __fadd_rn(aLo, aHi);
                    float es = fmaf(-2.f, dot, __fadd_rn(xq, ldcg(&g_ensq[idx])));
                    ull ek = mkkey(es, idx);
                    if (ek < ebest) ebest = ek;
                }
            }
        }
        o = __shfl_xor_sync(0xffffffffu, ebest, 1); ebest = o < ebest ? o : ebest;
        o = __shfl_xor_sync(0xffffffffu, ebest, 2); ebest = o < ebest ? o : ebest;

        int widx = (cnt == 1) ? (int)(m & 1023) : (int)(ebest & 1023);
        if ((lane & 3) == 0) {
            s_idx[trow] = widx;
            out[OFF_IDX + (size_t)(tok0 + trow)] = (float)widx;
            atomicAdd(&g_counts[widx], 1.f);
        }
    }
    __syncthreads();

    // --- gather codes -> quantized output + loss partial (float4 loads) ---
    float local = 0.f;
    {
        const float4* gx4 = (const float4*)(inputs + (size_t)tok0 * DIM);
#pragma unroll
        for (int it = 0; it < 8; ++it) {
            int t  = it * 16 + (tid >> 4);   // token 0..127
            int dq = tid & 15;               // float4 lane 0..15
            float4 qv = __ldg((const float4*)(weight + (size_t)s_idx[t] * DIM) + dq);
            float4 xv = __ldg(gx4 + t * 16 + dq);
            size_t ob = OFF_Q + (size_t)(tok0 + t) * DIM + dq * 4;
            out[ob]     = qv.x;
            out[ob + 1] = qv.y;
            out[ob + 2] = qv.z;
            out[ob + 3] = qv.w;
            float da = qv.x - xv.x, db = qv.y - xv.y;
            float dc = qv.z - xv.z, dd = qv.w - xv.w;
            local = fmaf(da, da, local);
            local = fmaf(db, db, local);
            local = fmaf(dc, dc, local);
            local = fmaf(dd, dd, local);
        }
    }
    s_part[tid] = local;
    __syncthreads();
    for (int off = 128; off > 0; off >>= 1) {
        if (tid < off) s_part[tid] += s_part[tid + off];
        __syncthreads();
    }
    if (tid == 0) atomicAdd(&g_loss_sum, s_part[0]);

    // --- last-block finalization (ticket) ---
    __threadfence();
    if (tid == 0) *s_tick = atomicAdd(&g_ticket, 1u);
    __syncthreads();
    if (*s_tick == (unsigned)(gridDim.x - 1)) {
        float acc_pl = 0.f;
#pragma unroll
        for (int rj = 0; rj < 4; ++rj) {
            float cnt = ldcg(&g_counts[tid + rj * NTHR]);
            float p = cnt * (1.f / 65536.f);
            acc_pl += p * logf(p + 1e-10f);
        }
        s_part[tid] = acc_pl;
        __syncthreads();
        for (int off = 128; off > 0; off >>= 1) {
            if (tid < off) s_part[tid] += s_part[tid + off];
            __syncthreads();
        }
        if (tid == 0) {
            float ls = ldcg(&g_loss_sum);
            out[0]       = 1.25f * ls * (1.f / (float)(N_TOKENS * DIM));
            out[OFF_PPL] = expf(-s_part[0]);
            g_loss_sum = 0.f;
            g_ticket   = 0u;
        }
#pragma unroll
        for (int rj = 0; rj < 4; ++rj) g_counts[tid + rj * NTHR] = 0.f;
    }
}

// ---------------------------------------------------------------------------
extern "C" void kernel_launch(void* const* d_in, const int* in_sizes, int n_in,
                              void* d_out, int out_size) {
    const float* inputs = (const float*)d_in[0];   // [64,32,32,64] fp32
    const float* weight = (const float*)d_in[1];   // [1024,64] fp32
    float* out = (float*)d_out;

    cudaFuncSetAttribute(k_main, cudaFuncAttributeMaxDynamicSharedMemorySize, SM_TOTAL);
    k_prep<<<16, 256>>>(weight);
    k_main<<<N_TOKENS / BM, NTHR, SM_TOTAL>>>(inputs, weight, out);
}